// round 13
// baseline (speedup 1.0000x reference)
#include <cuda_runtime.h>
#include <cuda_bf16.h>
#include <cstdint>

// PairExcludeMask: out[f,i,n] = type_mask[ atype[f,i]*9 + tj ]
//   tj = (nlist[f,i,n] == -1) ? 8 : atype[f, nlist[f,i,n]]
//
// pack_kernel (primary): nibble table -- 8 atom types per u32, 16KB/frame.
// mask_kernel (secondary, PDL): launches while pack runs. ONLY thread 0 of
// each block waits on the grid dependency (it alone issues the TMA read of
// pack's table); all other threads run the pack-independent prologue
// (rowinfo from atype+tmask, predicated nlist loads, fast-path stores) in
// parallel with both pack and the TMA. The mbarrier orders the slow path.

static constexpr int NF     = 4;
static constexpr int NLOC   = 16384;
static constexpr int NNEI   = 128;
static constexpr int NALL   = 32768;
static constexpr int NTYPES = 8;
static constexpr int TM1    = NTYPES + 1;          // 9
static constexpr uint32_t FULL = (1u << TM1) - 1;  // 0x1FF
static constexpr uint32_t ONEF = 0x3F800000u;      // 1.0f bits

static constexpr int WORDS   = NALL / 8;           // 4096 nibble words / frame
static constexpr int WORDS_P = WORDS + 4;          // + virtual atom + pad
static constexpr int TBL_BYTES = WORDS_P * 4;      // 16400

__device__ __align__(16) uint32_t g_nib[NF][WORDS_P];

// ---------------- kernel 1 (primary): pack nibbles ----------------
static constexpr int PK_THREADS = 128;
static constexpr int PK_BLOCKS  = NF * WORDS / PK_THREADS;   // 128

__global__ __launch_bounds__(PK_THREADS)
void pack_kernel(const int* __restrict__ atype)
{
    const int idx = blockIdx.x * PK_THREADS + threadIdx.x;   // 0 .. NF*WORDS-1
    const int f  = idx >> 12;                         // / WORDS
    const int wi = idx & (WORDS - 1);
    const int4* __restrict__ at4 = (const int4*)(atype + f * NALL);
    int4 a = at4[wi * 2];
    int4 b = at4[wi * 2 + 1];
    uint32_t p = (uint32_t)a.x        | ((uint32_t)a.y << 4)
               | ((uint32_t)a.z << 8) | ((uint32_t)a.w << 12)
               | ((uint32_t)b.x << 16)| ((uint32_t)b.y << 20)
               | ((uint32_t)b.z << 24)| ((uint32_t)b.w << 28);
    g_nib[f][wi] = p;
    if (wi == 0) {                                    // virtual atom j == NALL
        g_nib[f][WORDS]     = (uint32_t)NTYPES;       // nibble 0 = type 8
        g_nib[f][WORDS + 1] = 0;
        g_nib[f][WORDS + 2] = 0;
        g_nib[f][WORDS + 3] = 0;
    }
}

// ---------------- kernel 2 (secondary, PDL): stream the mask ----------------
static constexpr int THREADS_B = 512;
static constexpr int BPF       = 256;                      // blocks per frame
static constexpr int ROWS_PB   = NLOC / BPF;               // 64 rows / block
static constexpr int ROW_VEC   = NNEI / 4;                 // 32 vec4 per row
static constexpr int VEC_PB    = ROWS_PB * ROW_VEC;        // 2048
static constexpr int ITERS     = VEC_PB / THREADS_B;       // 4
static constexpr int BLOCKS_B  = NF * BPF;                 // 1024

static constexpr int SMEM_DYN  = TBL_BYTES;                // 16.4 KB

__global__ __launch_bounds__(THREADS_B)
void mask_kernel(const int4* __restrict__ nlist4,
                 const int*  __restrict__ atype,
                 const float* __restrict__ tmask,
                 uint4* __restrict__ out4)
{
    extern __shared__ __align__(16) uint32_t s_nib[];   // [WORDS_P]
    __shared__ __align__(8) unsigned long long s_mbar;
    __shared__ uint32_t s_rowinfo[ROWS_PB];             // (flag<<16) | rw

    const int tid  = threadIdx.x;
    const int f    = blockIdx.x >> 8;              // / BPF
    const int row0 = (blockIdx.x & (BPF - 1)) * ROWS_PB;

    uint32_t mbar_addr;
    asm("{ .reg .u64 t; cvta.to.shared.u64 t, %1; cvt.u32.u64 %0, t; }"
        : "=r"(mbar_addr) : "l"(&s_mbar));
    uint32_t dst_addr;
    asm("{ .reg .u64 t; cvta.to.shared.u64 t, %1; cvt.u32.u64 %0, t; }"
        : "=r"(dst_addr) : "l"(s_nib));

    if (tid == 0)
        asm volatile("mbarrier.init.shared.b64 [%0], 1;" :: "r"(mbar_addr) : "memory");
    __syncthreads();                               // mbarrier visible

    // Only the TMA-issuing thread waits for pack's output; the rest of the
    // block runs the pack-independent prologue concurrently.
    if (tid == 0) {
        cudaGridDependencySynchronize();
        asm volatile("mbarrier.arrive.expect_tx.shared.b64 _, [%0], %1;"
                     :: "r"(mbar_addr), "r"((uint32_t)TBL_BYTES) : "memory");
        asm volatile("cp.async.bulk.shared::cluster.global.mbarrier::complete_tx::bytes "
                     "[%0], [%1], %2, [%3];"
                     :: "r"(dst_addr), "l"(g_nib[f]),
                        "r"((uint32_t)TBL_BYTES), "r"(mbar_addr) : "memory");
    }

    // ---- pack-independent prologue (overlaps pack + the TMA copy) ----
    if (tid < ROWS_PB) {
        const int ti = __ldg(atype + f * NALL + row0 + tid);
        uint32_t w = 0;
        #pragma unroll
        for (int tj = 0; tj < TM1; ++tj)
            w |= (__ldg(tmask + ti * TM1 + tj) != 0.0f ? 1u : 0u) << tj;
        const uint32_t flag = (w == FULL) ? 1u : ((w == 0u) ? 0u : 2u);
        s_rowinfo[tid] = (flag << 16) | w;
    }
    __syncthreads();                               // rowinfo visible

    const size_t base = ((size_t)f * NLOC + row0) * ROW_VEC;
    const int4*  __restrict__ nl = nlist4 + base;
    uint4*       __restrict__ ob = out4  + base;

    uint32_t info[ITERS];
    #pragma unroll
    for (int k = 0; k < ITERS; ++k)
        info[k] = s_rowinfo[(tid + k * THREADS_B) >> 5];

    int4 nj[ITERS];
    #pragma unroll
    for (int k = 0; k < ITERS; ++k)
        if ((info[k] >> 16) == 2u)
            nj[k] = nl[tid + k * THREADS_B];

    #pragma unroll
    for (int k = 0; k < ITERS; ++k) {
        const uint32_t flag = info[k] >> 16;
        if (flag != 2u) {
            const uint32_t b = (flag == 1u) ? ONEF : 0u;
            ob[tid + k * THREADS_B] = make_uint4(b, b, b, b);
        }
    }

    // ---- wait for the nibble table ----
    {
        uint32_t done;
        asm volatile(
            "{\n\t.reg .pred p;\n\t"
            "mbarrier.try_wait.parity.acquire.cta.shared::cta.b64 p, [%1], 0;\n\t"
            "selp.b32 %0, 1, 0, p;\n\t}"
            : "=r"(done) : "r"(mbar_addr) : "memory");
        while (!done) {
            asm volatile(
                "{\n\t.reg .pred p;\n\t"
                "mbarrier.try_wait.parity.acquire.cta.shared::cta.b64 p, [%1], 0, 0x989680;\n\t"
                "selp.b32 %0, 1, 0, p;\n\t}"
                : "=r"(done) : "r"(mbar_addr) : "memory");
        }
    }

    // ---- slow path: gather + store ----
    #pragma unroll
    for (int k = 0; k < ITERS; ++k) {
        if ((info[k] >> 16) != 2u) continue;
        const int v = tid + k * THREADS_B;
        const uint32_t rw = info[k] & 0xFFFFu;     // 9-bit row word (warp-uniform)

        uint32_t j0 = min((uint32_t)nj[k].x, (uint32_t)NALL);
        uint32_t j1 = min((uint32_t)nj[k].y, (uint32_t)NALL);
        uint32_t j2 = min((uint32_t)nj[k].z, (uint32_t)NALL);
        uint32_t j3 = min((uint32_t)nj[k].w, (uint32_t)NALL);

        uint32_t w0 = s_nib[j0 >> 3];
        uint32_t w1 = s_nib[j1 >> 3];
        uint32_t w2 = s_nib[j2 >> 3];
        uint32_t w3 = s_nib[j3 >> 3];

        uint32_t t0 = (w0 >> ((j0 & 7u) << 2)) & 15u;
        uint32_t t1 = (w1 >> ((j1 & 7u) << 2)) & 15u;
        uint32_t t2 = (w2 >> ((j2 & 7u) << 2)) & 15u;
        uint32_t t3 = (w3 >> ((j3 & 7u) << 2)) & 15u;

        uint4 r;
        r.x = ((rw >> t0) & 1u) ? ONEF : 0u;
        r.y = ((rw >> t1) & 1u) ? ONEF : 0u;
        r.z = ((rw >> t2) & 1u) ? ONEF : 0u;
        r.w = ((rw >> t3) & 1u) ? ONEF : 0u;

        ob[v] = r;
    }
}

extern "C" void kernel_launch(void* const* d_in, const int* in_sizes, int n_in,
                              void* d_out, int out_size)
{
    const int4*  nlist4 = (const int4*) d_in[0];
    const int*   atype  = (const int*)  d_in[1];
    const float* tmask  = (const float*)d_in[2];
    // d_in[3] = ntypes scalar (8, baked into constants)

    uint4* out4 = (uint4*)d_out;

    static bool configured = false;
    if (!configured) {
        cudaFuncSetAttribute(mask_kernel,
                             cudaFuncAttributeMaxDynamicSharedMemorySize,
                             SMEM_DYN);
        cudaFuncSetAttribute(mask_kernel,
                             cudaFuncAttributePreferredSharedMemoryCarveout,
                             100);
        configured = true;
    }

    pack_kernel<<<PK_BLOCKS, PK_THREADS>>>(atype);

    // PDL: mask_kernel starts while pack_kernel is still running; only the
    // TMA-issuing thread of each block waits on the grid dependency.
    cudaLaunchConfig_t cfg = {};
    cfg.gridDim  = dim3(BLOCKS_B, 1, 1);
    cfg.blockDim = dim3(THREADS_B, 1, 1);
    cfg.dynamicSmemBytes = SMEM_DYN;
    cfg.stream = 0;
    cudaLaunchAttribute attr[1];
    attr[0].id = cudaLaunchAttributeProgrammaticStreamSerialization;
    attr[0].val.programmaticStreamSerializationAllowed = 1;
    cfg.attrs = attr;
    cfg.numAttrs = 1;
    cudaLaunchKernelEx(&cfg, mask_kernel, nlist4, atype, tmask, out4);
}